// round 11
// baseline (speedup 1.0000x reference)
#include <cuda_runtime.h>

#define BATCH 128
#define SEQ   2000
#define EMB   50
#define VOCAB 1000000
#define SPLIT 16
#define CHUNK (SEQ / SPLIT)      // 125 tokens per block
#define WARPS 8
#define THREADS (WARPS * 32)
#define HALF_EMB 25              // 25 float2 per row

// Cross-block accumulators (zero-init at module load; each launch leaves them
// zeroed again after use -> graph-replay safe, no zeroing pass needed).
__device__ float g_accum[BATCH][2];
__device__ int   g_cnt[BATCH];

__global__ __launch_bounds__(THREADS) void fused_kernel(
    const int* __restrict__ t32, const float* __restrict__ emb,
    const float* __restrict__ W, const float* __restrict__ bias,
    float* __restrict__ out)
{
    const int b     = blockIdx.y;
    const int chunk = blockIdx.x;
    const int warp  = threadIdx.x >> 5;
    const int lane  = threadIdx.x & 31;

    // ---- inline dtype detect (warp 0: 1 parallel load + ballot) ----
    // int64 indices in [-1, 1e6): every odd 32-bit word is 0 or -1.
    __shared__ int s_is64;
    if (threadIdx.x < 32) {
        const unsigned int hi =
            reinterpret_cast<const unsigned int*>(t32)[2 * lane + 1];
        const bool ok = (hi == 0u) || (hi == 0xFFFFFFFFu);
        const unsigned m = __ballot_sync(0xFFFFFFFFu, ok);
        if (lane == 0) s_is64 = (m == 0xFFFFFFFFu) ? 1 : 0;
    }
    __syncthreads();
    const int stride = s_is64 ? 2 : 1;   // 32-bit-word stride per index

    const int* trow = t32 + ((long long)b * SEQ + (long long)chunk * CHUNK) * stride;

    const bool active = (lane < HALF_EMB);
    const int  foff   = 2 * lane;        // float offset within an embedding row

    float2 a0 = make_float2(0.f, 0.f);
    float2 a1 = make_float2(0.f, 0.f);
    float2 a2 = make_float2(0.f, 0.f);
    float2 a3 = make_float2(0.f, 0.f);

    int s = warp;
    // 4 independent gather streams per lane.
    for (; s + 3 * WARPS < CHUNK; s += 4 * WARPS) {
        const int v0 = trow[(s)             * stride];
        const int v1 = trow[(s +     WARPS) * stride];
        const int v2 = trow[(s + 2 * WARPS) * stride];
        const int v3 = trow[(s + 3 * WARPS) * stride];
        if (active) {
            if ((unsigned)v0 < (unsigned)VOCAB) {
                const float2 e = *reinterpret_cast<const float2*>(
                    emb + (long long)v0 * EMB + foff);
                a0.x += e.x; a0.y += e.y;
            }
            if ((unsigned)v1 < (unsigned)VOCAB) {
                const float2 e = *reinterpret_cast<const float2*>(
                    emb + (long long)v1 * EMB + foff);
                a1.x += e.x; a1.y += e.y;
            }
            if ((unsigned)v2 < (unsigned)VOCAB) {
                const float2 e = *reinterpret_cast<const float2*>(
                    emb + (long long)v2 * EMB + foff);
                a2.x += e.x; a2.y += e.y;
            }
            if ((unsigned)v3 < (unsigned)VOCAB) {
                const float2 e = *reinterpret_cast<const float2*>(
                    emb + (long long)v3 * EMB + foff);
                a3.x += e.x; a3.y += e.y;
            }
        }
    }
    for (; s < CHUNK; s += WARPS) {
        const int v = trow[s * stride];
        if (active && (unsigned)v < (unsigned)VOCAB) {
            const float2 e = *reinterpret_cast<const float2*>(
                emb + (long long)v * EMB + foff);
            a0.x += e.x; a0.y += e.y;
        }
    }
    a0.x += a1.x + a2.x + a3.x;
    a0.y += a1.y + a2.y + a3.y;

    // Block reduction across the 8 warps (per embedding-pair slot j = lane).
    __shared__ float2 red[WARPS][HALF_EMB];
    if (active) red[warp][lane] = a0;
    __syncthreads();

    // Warp 0: fold 25 slots into the 2 output dot products, then the
    // cross-block epilogue via atomics (last block for this b finalizes).
    if (warp == 0) {
        float c0 = 0.f, c1 = 0.f;
        if (active) {
            const int j = lane;
            const float w00 = __ldg(&W[2 * j]);
            const float w01 = __ldg(&W[2 * j + 1]);
            const float w10 = __ldg(&W[EMB + 2 * j]);
            const float w11 = __ldg(&W[EMB + 2 * j + 1]);
            float2 sum = red[0][j];
            #pragma unroll
            for (int w = 1; w < WARPS; w++) {
                sum.x += red[w][j].x;
                sum.y += red[w][j].y;
            }
            c0 = sum.x * w00 + sum.y * w01;
            c1 = sum.x * w10 + sum.y * w11;
        }
        #pragma unroll
        for (int off = 16; off > 0; off >>= 1) {
            c0 += __shfl_down_sync(0xFFFFFFFFu, c0, off);
            c1 += __shfl_down_sync(0xFFFFFFFFu, c1, off);
        }

        if (lane == 0) {
            atomicAdd(&g_accum[b][0], c0);
            atomicAdd(&g_accum[b][1], c1);
            __threadfence();                       // release accum before count
            const int prev = atomicAdd(&g_cnt[b], 1);
            if (prev == SPLIT - 1) {               // last block for this b
                __threadfence();                   // acquire all accum adds
                const float s0 = g_accum[b][0];
                const float s1 = g_accum[b][1];
                const float scale = 1.0f / (float)BATCH;  // ref divides by len(t)
                out[2 * b + 0] = fmaxf(bias[0] + scale * s0, 0.0f);
                out[2 * b + 1] = fmaxf(bias[1] + scale * s1, 0.0f);
                // Reset for the next graph replay.
                g_accum[b][0] = 0.f;
                g_accum[b][1] = 0.f;
                __threadfence();
                g_cnt[b] = 0;
            }
        }
    }
}

extern "C" void kernel_launch(void* const* d_in, const int* in_sizes, int n_in,
                              void* d_out, int out_size)
{
    const int*   t32 = (const int*)d_in[0];        // int32 OR int64 [128, 2000]
    const float* emb = (const float*)d_in[1];      // f32 [1e6, 50]
    const float* W   = (const float*)d_in[2];      // f32 [2, 50]
    const float* bia = (const float*)d_in[3];      // f32 [2]
    float*       out = (float*)d_out;              // f32 [128, 2]

    dim3 grid(SPLIT, BATCH);
    fused_kernel<<<grid, THREADS>>>(t32, emb, W, bia, out);
}

// round 12
// speedup vs baseline: 1.1145x; 1.1145x over previous
#include <cuda_runtime.h>

#define BATCH 128
#define SEQ   2000
#define EMB   50
#define VOCAB 1000000
#define SPLIT 5
#define CHUNK (SEQ / SPLIT)      // 400 tokens per block
#define WARPS 8
#define THREADS (WARPS * 32)
#define TPW (CHUNK / WARPS)      // 50 tokens per warp (contiguous)
#define HALF_EMB 25              // 25 float2 per row
#define MLP 8                    // gather streams in flight per lane

// Cross-block accumulators (zero-init at module load; each launch leaves them
// zeroed again -> graph-replay safe, no zeroing pass).
__device__ float g_accum[BATCH][2];
__device__ int   g_cnt[BATCH];

__global__ __launch_bounds__(THREADS) void fused_kernel(
    const int* __restrict__ t32, const float* __restrict__ emb,
    const float* __restrict__ W, const float* __restrict__ bias,
    float* __restrict__ out)
{
    const int b     = blockIdx.y;
    const int chunk = blockIdx.x;
    const int warp  = threadIdx.x >> 5;
    const int lane  = threadIdx.x & 31;

    // ---- inline dtype detect (warp 0: 1 parallel load + ballot) ----
    // int64 indices in [-1, 1e6): every odd 32-bit word is 0 or -1.
    __shared__ int s_is64;
    if (threadIdx.x < 32) {
        const unsigned int hi =
            reinterpret_cast<const unsigned int*>(t32)[2 * lane + 1];
        const bool ok = (hi == 0u) || (hi == 0xFFFFFFFFu);
        const unsigned m = __ballot_sync(0xFFFFFFFFu, ok);
        if (lane == 0) s_is64 = (m == 0xFFFFFFFFu) ? 1 : 0;
    }
    __syncthreads();
    const int stride = s_is64 ? 2 : 1;   // 32-bit-word stride per index

    // Per-warp contiguous token range within this block's chunk.
    const int* trow = t32 +
        ((long long)b * SEQ + (long long)chunk * CHUNK + (long long)warp * TPW)
        * stride;

    const bool active = (lane < HALF_EMB);
    const int  lp     = active ? lane : 0;   // inactive lanes: free broadcast of chunk 0
    const float2* __restrict__ emb2 = reinterpret_cast<const float2*>(emb);

    float2 accA = make_float2(0.f, 0.f);
    float2 accB = make_float2(0.f, 0.f);

    int s = 0;
    // 8 unconditional gathers in flight per lane (invalid idx clamped to row 0,
    // contribution dropped at accumulate time).
    for (; s + MLP <= TPW; s += MLP) {
        int vb[MLP];
        #pragma unroll
        for (int i = 0; i < MLP; i++)
            vb[i] = trow[(s + i) * stride];       // warp-uniform broadcast

        float2 t[MLP];
        #pragma unroll
        for (int i = 0; i < MLP; i++) {
            const int safe = ((unsigned)vb[i] < (unsigned)VOCAB) ? vb[i] : 0;
            t[i] = emb2[safe * HALF_EMB + lp];    // fits in 32-bit arithmetic
        }

        #pragma unroll
        for (int i = 0; i < MLP; i++) {
            if (active && (unsigned)vb[i] < (unsigned)VOCAB) {
                if (i & 1) { accB.x += t[i].x; accB.y += t[i].y; }
                else       { accA.x += t[i].x; accA.y += t[i].y; }
            }
        }
    }
    for (; s < TPW; s++) {                        // remainder (2 tokens)
        const int v = trow[s * stride];
        if (active && (unsigned)v < (unsigned)VOCAB) {
            const float2 e = emb2[v * HALF_EMB + lp];
            accA.x += e.x; accA.y += e.y;
        }
    }
    accA.x += accB.x;
    accA.y += accB.y;

    // Block reduction across the 8 warps (per embedding-pair slot j = lane).
    __shared__ float2 red[WARPS][HALF_EMB];
    if (active) red[warp][lane] = accA;
    __syncthreads();

    // Warp 0: fold 25 slots into the 2 output dot products, then the
    // cross-block epilogue via atomics (last block for this b finalizes).
    if (warp == 0) {
        float c0 = 0.f, c1 = 0.f;
        if (active) {
            const int j = lane;
            const float w00 = __ldg(&W[2 * j]);
            const float w01 = __ldg(&W[2 * j + 1]);
            const float w10 = __ldg(&W[EMB + 2 * j]);
            const float w11 = __ldg(&W[EMB + 2 * j + 1]);
            float2 sum = red[0][j];
            #pragma unroll
            for (int w = 1; w < WARPS; w++) {
                sum.x += red[w][j].x;
                sum.y += red[w][j].y;
            }
            c0 = sum.x * w00 + sum.y * w01;
            c1 = sum.x * w10 + sum.y * w11;
        }
        #pragma unroll
        for (int off = 16; off > 0; off >>= 1) {
            c0 += __shfl_down_sync(0xFFFFFFFFu, c0, off);
            c1 += __shfl_down_sync(0xFFFFFFFFu, c1, off);
        }

        if (lane == 0) {
            atomicAdd(&g_accum[b][0], c0);
            atomicAdd(&g_accum[b][1], c1);
            __threadfence();                       // release accum before count
            const int prev = atomicAdd(&g_cnt[b], 1);
            if (prev == SPLIT - 1) {               // last block for this b
                __threadfence();                   // acquire all accum adds
                const float s0 = g_accum[b][0];
                const float s1 = g_accum[b][1];
                const float scale = 1.0f / (float)BATCH;  // ref divides by len(t)
                out[2 * b + 0] = fmaxf(bias[0] + scale * s0, 0.0f);
                out[2 * b + 1] = fmaxf(bias[1] + scale * s1, 0.0f);
                // Reset for the next graph replay.
                g_accum[b][0] = 0.f;
                g_accum[b][1] = 0.f;
                __threadfence();
                g_cnt[b] = 0;
            }
        }
    }
}

extern "C" void kernel_launch(void* const* d_in, const int* in_sizes, int n_in,
                              void* d_out, int out_size)
{
    const int*   t32 = (const int*)d_in[0];        // int32 OR int64 [128, 2000]
    const float* emb = (const float*)d_in[1];      // f32 [1e6, 50]
    const float* W   = (const float*)d_in[2];      // f32 [2, 50]
    const float* bia = (const float*)d_in[3];      // f32 [2]
    float*       out = (float*)d_out;              // f32 [128, 2]

    dim3 grid(SPLIT, BATCH);                       // 640 CTAs ~= one full wave
    fused_kernel<<<grid, THREADS>>>(t32, emb, W, bia, out);
}